// round 1
// baseline (speedup 1.0000x reference)
#include <cuda_runtime.h>

// ---------------------------------------------------------------------------
// Fused MHA forward: x@Wq/Wk/Wv -> flash attention -> @Wo
// B=2, S=2048, D=1024, H=16, Hd=64, fp32.
// Round 0: fp32 SIMT baseline. 64x64 tiled GEMMs (4x4/thread), flash attn
// with online softmax. Structure chosen so tensor-core swap is incremental.
// ---------------------------------------------------------------------------

#define D_MODEL 1024
#define NHEADS  16
#define HD      64
#define BATCH   2
#define SEQ     2048
#define MTOT    (BATCH * SEQ)   // 4096

// Scratch (allocation-free rule: __device__ globals)
__device__ float g_q[BATCH * NHEADS * SEQ * HD];   // [b,h,s,d]
__device__ float g_k[BATCH * NHEADS * SEQ * HD];
__device__ float g_v[BATCH * NHEADS * SEQ * HD];
__device__ float g_att[MTOT * D_MODEL];            // [b,s, h*HD+d]

// ---------------------------------------------------------------------------
// QKV projection GEMM: C = x @ W + b, written in split-head layout.
// Tile: 64(M) x 64(N) x 16(K), 256 threads, 4x4 accum per thread.
// SMEM A stored transposed [k][m] so both operands are LDS.128 in the loop.
// grid.z in {0,1,2} selects Q/K/V.
// ---------------------------------------------------------------------------
__global__ __launch_bounds__(256) void qkv_gemm(
    const float* __restrict__ x,
    const float* __restrict__ Wq, const float* __restrict__ bq,
    const float* __restrict__ Wk, const float* __restrict__ bk,
    const float* __restrict__ Wv, const float* __restrict__ bv)
{
    const float* W;
    const float* bias;
    float* outp;
    if (blockIdx.z == 0)      { W = Wq; bias = bq; outp = g_q; }
    else if (blockIdx.z == 1) { W = Wk; bias = bk; outp = g_k; }
    else                      { W = Wv; bias = bv; outp = g_v; }

    __shared__ float As[16][64];   // [k][m]
    __shared__ float Ws[16][64];   // [k][n]

    const int tid = threadIdx.x;
    const int tx = tid & 15, ty = tid >> 4;
    const int bm = blockIdx.y * 64;
    const int bn = blockIdx.x * 64;

    const int arow = tid >> 2, aquad = tid & 3;    // A loader: 64 rows x 4 quads
    const int wrow = tid >> 4, wquad = tid & 15;   // W loader: 16 rows x 16 quads

    float acc[4][4] = {};

    for (int k0 = 0; k0 < D_MODEL; k0 += 16) {
        // Issue global loads before the sync so latency overlaps prior compute
        float4 av = *reinterpret_cast<const float4*>(x + (bm + arow) * D_MODEL + k0 + aquad * 4);
        float4 wv = *reinterpret_cast<const float4*>(W + (k0 + wrow) * D_MODEL + bn + wquad * 4);
        __syncthreads();
        As[aquad * 4 + 0][arow] = av.x;
        As[aquad * 4 + 1][arow] = av.y;
        As[aquad * 4 + 2][arow] = av.z;
        As[aquad * 4 + 3][arow] = av.w;
        *reinterpret_cast<float4*>(&Ws[wrow][wquad * 4]) = wv;
        __syncthreads();

#pragma unroll
        for (int k = 0; k < 16; ++k) {
            float4 a = *reinterpret_cast<const float4*>(&As[k][ty * 4]);
            float4 w = *reinterpret_cast<const float4*>(&Ws[k][tx * 4]);
            acc[0][0] += a.x * w.x; acc[0][1] += a.x * w.y; acc[0][2] += a.x * w.z; acc[0][3] += a.x * w.w;
            acc[1][0] += a.y * w.x; acc[1][1] += a.y * w.y; acc[1][2] += a.y * w.z; acc[1][3] += a.y * w.w;
            acc[2][0] += a.z * w.x; acc[2][1] += a.z * w.y; acc[2][2] += a.z * w.z; acc[2][3] += a.z * w.w;
            acc[3][0] += a.w * w.x; acc[3][1] += a.w * w.y; acc[3][2] += a.w * w.z; acc[3][3] += a.w * w.w;
        }
    }

    // N-tile == HD == 64, so head index == blockIdx.x
    const int h = blockIdx.x;
    const float4 bb = *reinterpret_cast<const float4*>(bias + bn + tx * 4);
#pragma unroll
    for (int i = 0; i < 4; ++i) {
        int m = bm + ty * 4 + i;
        int b_ = m >> 11;            // / SEQ
        int s_ = m & (SEQ - 1);
        float4 r;
        r.x = acc[i][0] + bb.x;
        r.y = acc[i][1] + bb.y;
        r.z = acc[i][2] + bb.z;
        r.w = acc[i][3] + bb.w;
        *reinterpret_cast<float4*>(outp + ((size_t)((b_ * NHEADS + h) * SEQ + s_)) * HD + tx * 4) = r;
    }
}

// ---------------------------------------------------------------------------
// Flash attention: one block = (b,h) x 64 query rows, loops over 32 key tiles.
// Q/K stored d-transposed in SMEM -> score loop is 2x LDS.128 + 16 FMA per d.
// Online softmax state (m, l) per row, in registers.
// ---------------------------------------------------------------------------
#define ATTN_SMEM ((3 * 64 * 64 + 64 * 65) * 4)

__global__ __launch_bounds__(256) void attn_kernel()
{
    extern __shared__ float sm[];
    float* Qt = sm;                 // [d][r]  64x64
    float* Kt = sm + 64 * 64;       // [d][c]  64x64
    float* Vs = sm + 2 * 64 * 64;   // [c][d]  64x64
    float* Pt = sm + 3 * 64 * 64;   // [c][r]  64x65 (pad: 2-way conflicts max)

    const int tid = threadIdx.x;
    const int tx = tid & 15, ty = tid >> 4;
    const int bh = blockIdx.y;                 // b*H + h
    const int q0 = blockIdx.x * 64;

    const float* Qg = g_q + ((size_t)bh * SEQ + q0) * HD;
    const float* Kg = g_k + (size_t)bh * SEQ * HD;
    const float* Vg = g_v + (size_t)bh * SEQ * HD;

    const float scale = 0.125f;   // 1/sqrt(64), folded into Q at load

    // Load Q tile transposed (and pre-scaled)
    for (int i = tid; i < 64 * 16; i += 256) {
        int r = i >> 4, quad = i & 15;
        float4 v = *reinterpret_cast<const float4*>(Qg + r * HD + quad * 4);
        Qt[(quad * 4 + 0) * 64 + r] = v.x * scale;
        Qt[(quad * 4 + 1) * 64 + r] = v.y * scale;
        Qt[(quad * 4 + 2) * 64 + r] = v.z * scale;
        Qt[(quad * 4 + 3) * 64 + r] = v.w * scale;
    }

    float o[4][4] = {};
    float mrow[4] = {-1e30f, -1e30f, -1e30f, -1e30f};
    float lrow[4] = {0.f, 0.f, 0.f, 0.f};

    for (int kt = 0; kt < SEQ / 64; ++kt) {
        const float* Kgt = Kg + kt * 64 * HD;
        const float* Vgt = Vg + kt * 64 * HD;

        __syncthreads();   // previous PV done with Vs/Pt, scores done with Kt
        for (int i = tid; i < 64 * 16; i += 256) {
            int r = i >> 4, quad = i & 15;
            float4 v = *reinterpret_cast<const float4*>(Kgt + r * HD + quad * 4);
            Kt[(quad * 4 + 0) * 64 + r] = v.x;
            Kt[(quad * 4 + 1) * 64 + r] = v.y;
            Kt[(quad * 4 + 2) * 64 + r] = v.z;
            Kt[(quad * 4 + 3) * 64 + r] = v.w;
            float4 vv = *reinterpret_cast<const float4*>(Vgt + r * HD + quad * 4);
            *reinterpret_cast<float4*>(&Vs[r * 64 + quad * 4]) = vv;
        }
        __syncthreads();

        // Scores: s[i][j] = sum_d Qt[d][4ty+i] * Kt[d][4tx+j]
        float s4[4][4] = {};
#pragma unroll 16
        for (int d = 0; d < 64; ++d) {
            float4 qv = *reinterpret_cast<const float4*>(&Qt[d * 64 + ty * 4]);
            float4 kv = *reinterpret_cast<const float4*>(&Kt[d * 64 + tx * 4]);
            s4[0][0] += qv.x * kv.x; s4[0][1] += qv.x * kv.y; s4[0][2] += qv.x * kv.z; s4[0][3] += qv.x * kv.w;
            s4[1][0] += qv.y * kv.x; s4[1][1] += qv.y * kv.y; s4[1][2] += qv.y * kv.z; s4[1][3] += qv.y * kv.w;
            s4[2][0] += qv.z * kv.x; s4[2][1] += qv.z * kv.y; s4[2][2] += qv.z * kv.z; s4[2][3] += qv.z * kv.w;
            s4[3][0] += qv.w * kv.x; s4[3][1] += qv.w * kv.y; s4[3][2] += qv.w * kv.z; s4[3][3] += qv.w * kv.w;
        }

        // Online softmax per row; xor-shuffle over the 16 tx lanes
#pragma unroll
        for (int i = 0; i < 4; ++i) {
            float mx = fmaxf(fmaxf(s4[i][0], s4[i][1]), fmaxf(s4[i][2], s4[i][3]));
#pragma unroll
            for (int off = 1; off <= 8; off <<= 1)
                mx = fmaxf(mx, __shfl_xor_sync(0xffffffffu, mx, off, 32));
            float mnew = fmaxf(mrow[i], mx);
            float alpha = __expf(mrow[i] - mnew);
            mrow[i] = mnew;
            float rs = 0.f;
#pragma unroll
            for (int j = 0; j < 4; ++j) {
                s4[i][j] = __expf(s4[i][j] - mnew);
                rs += s4[i][j];
            }
#pragma unroll
            for (int off = 1; off <= 8; off <<= 1)
                rs += __shfl_xor_sync(0xffffffffu, rs, off, 32);
            lrow[i] = lrow[i] * alpha + rs;
#pragma unroll
            for (int j = 0; j < 4; ++j) o[i][j] *= alpha;
            // Store P transposed: Pt[c][r]
#pragma unroll
            for (int j = 0; j < 4; ++j)
                Pt[(tx * 4 + j) * 65 + ty * 4 + i] = s4[i][j];
        }
        __syncthreads();

        // PV: o[i][j] += sum_c Pt[c][4ty+i] * Vs[c][4tx+j]
#pragma unroll 16
        for (int c = 0; c < 64; ++c) {
            float p0 = Pt[c * 65 + ty * 4 + 0];
            float p1 = Pt[c * 65 + ty * 4 + 1];
            float p2 = Pt[c * 65 + ty * 4 + 2];
            float p3 = Pt[c * 65 + ty * 4 + 3];
            float4 vv = *reinterpret_cast<const float4*>(&Vs[c * 64 + tx * 4]);
            o[0][0] += p0 * vv.x; o[0][1] += p0 * vv.y; o[0][2] += p0 * vv.z; o[0][3] += p0 * vv.w;
            o[1][0] += p1 * vv.x; o[1][1] += p1 * vv.y; o[1][2] += p1 * vv.z; o[1][3] += p1 * vv.w;
            o[2][0] += p2 * vv.x; o[2][1] += p2 * vv.y; o[2][2] += p2 * vv.z; o[2][3] += p2 * vv.w;
            o[3][0] += p3 * vv.x; o[3][1] += p3 * vv.y; o[3][2] += p3 * vv.z; o[3][3] += p3 * vv.w;
        }
    }

    // Epilogue: normalize and write attended in [b, s, h*HD+d] layout
    const int b_ = bh >> 4;
    const int h  = bh & 15;
#pragma unroll
    for (int i = 0; i < 4; ++i) {
        float inv = 1.0f / lrow[i];
        int q = q0 + ty * 4 + i;
        float4 r;
        r.x = o[i][0] * inv;
        r.y = o[i][1] * inv;
        r.z = o[i][2] * inv;
        r.w = o[i][3] * inv;
        *reinterpret_cast<float4*>(&g_att[((size_t)(b_ * SEQ + q)) * D_MODEL + h * HD + tx * 4]) = r;
    }
}

// ---------------------------------------------------------------------------
// Output projection: out = g_att @ Wo + bo   (row-major [4096,1024])
// ---------------------------------------------------------------------------
__global__ __launch_bounds__(256) void out_gemm(
    const float* __restrict__ Wo, const float* __restrict__ bo,
    float* __restrict__ out)
{
    __shared__ float As[16][64];
    __shared__ float Ws[16][64];

    const int tid = threadIdx.x;
    const int tx = tid & 15, ty = tid >> 4;
    const int bm = blockIdx.y * 64;
    const int bn = blockIdx.x * 64;

    const int arow = tid >> 2, aquad = tid & 3;
    const int wrow = tid >> 4, wquad = tid & 15;

    float acc[4][4] = {};

    for (int k0 = 0; k0 < D_MODEL; k0 += 16) {
        float4 av = *reinterpret_cast<const float4*>(g_att + ((size_t)(bm + arow)) * D_MODEL + k0 + aquad * 4);
        float4 wv = *reinterpret_cast<const float4*>(Wo + (k0 + wrow) * D_MODEL + bn + wquad * 4);
        __syncthreads();
        As[aquad * 4 + 0][arow] = av.x;
        As[aquad * 4 + 1][arow] = av.y;
        As[aquad * 4 + 2][arow] = av.z;
        As[aquad * 4 + 3][arow] = av.w;
        *reinterpret_cast<float4*>(&Ws[wrow][wquad * 4]) = wv;
        __syncthreads();

#pragma unroll
        for (int k = 0; k < 16; ++k) {
            float4 a = *reinterpret_cast<const float4*>(&As[k][ty * 4]);
            float4 w = *reinterpret_cast<const float4*>(&Ws[k][tx * 4]);
            acc[0][0] += a.x * w.x; acc[0][1] += a.x * w.y; acc[0][2] += a.x * w.z; acc[0][3] += a.x * w.w;
            acc[1][0] += a.y * w.x; acc[1][1] += a.y * w.y; acc[1][2] += a.y * w.z; acc[1][3] += a.y * w.w;
            acc[2][0] += a.z * w.x; acc[2][1] += a.z * w.y; acc[2][2] += a.z * w.z; acc[2][3] += a.z * w.w;
            acc[3][0] += a.w * w.x; acc[3][1] += a.w * w.y; acc[3][2] += a.w * w.z; acc[3][3] += a.w * w.w;
        }
    }

    const float4 bb = *reinterpret_cast<const float4*>(bo + bn + tx * 4);
#pragma unroll
    for (int i = 0; i < 4; ++i) {
        int m = bm + ty * 4 + i;
        float4 r;
        r.x = acc[i][0] + bb.x;
        r.y = acc[i][1] + bb.y;
        r.z = acc[i][2] + bb.z;
        r.w = acc[i][3] + bb.w;
        *reinterpret_cast<float4*>(out + (size_t)m * D_MODEL + bn + tx * 4) = r;
    }
}

// ---------------------------------------------------------------------------
extern "C" void kernel_launch(void* const* d_in, const int* in_sizes, int n_in,
                              void* d_out, int out_size)
{
    const float* x  = (const float*)d_in[0];
    const float* Wq = (const float*)d_in[1];
    const float* bq = (const float*)d_in[2];
    const float* Wk = (const float*)d_in[3];
    const float* bk = (const float*)d_in[4];
    const float* Wv = (const float*)d_in[5];
    const float* bv = (const float*)d_in[6];
    const float* Wo = (const float*)d_in[7];
    const float* bo = (const float*)d_in[8];
    float* out = (float*)d_out;

    // 1) QKV projections (fused over grid.z)
    dim3 g1(D_MODEL / 64, MTOT / 64, 3);   // 16 x 64 x 3
    qkv_gemm<<<g1, 256>>>(x, Wq, bq, Wk, bk, Wv, bv);

    // 2) Flash attention
    cudaFuncSetAttribute(attn_kernel, cudaFuncAttributeMaxDynamicSharedMemorySize, ATTN_SMEM);
    dim3 g2(SEQ / 64, BATCH * NHEADS);     // 32 x 32
    attn_kernel<<<g2, 256, ATTN_SMEM>>>();

    // 3) Output projection
    dim3 g3(D_MODEL / 64, MTOT / 64);      // 16 x 64
    out_gemm<<<g3, 256>>>(Wo, bo, out);
}

// round 2
// speedup vs baseline: 1.0001x; 1.0001x over previous
#include <cuda_runtime.h>

// ---------------------------------------------------------------------------
// Fused MHA forward: x@Wq/Wk/Wv -> flash attention -> @Wo
// B=2, S=2048, D=1024, H=16, Hd=64, fp32.
// Round 0: fp32 SIMT baseline. 64x64 tiled GEMMs (4x4/thread), flash attn
// with online softmax. Structure chosen so tensor-core swap is incremental.
// ---------------------------------------------------------------------------

#define D_MODEL 1024
#define NHEADS  16
#define HD      64
#define BATCH   2
#define SEQ     2048
#define MTOT    (BATCH * SEQ)   // 4096

// Scratch (allocation-free rule: __device__ globals)
__device__ float g_q[BATCH * NHEADS * SEQ * HD];   // [b,h,s,d]
__device__ float g_k[BATCH * NHEADS * SEQ * HD];
__device__ float g_v[BATCH * NHEADS * SEQ * HD];
__device__ float g_att[MTOT * D_MODEL];            // [b,s, h*HD+d]

// ---------------------------------------------------------------------------
// QKV projection GEMM: C = x @ W + b, written in split-head layout.
// Tile: 64(M) x 64(N) x 16(K), 256 threads, 4x4 accum per thread.
// SMEM A stored transposed [k][m] so both operands are LDS.128 in the loop.
// grid.z in {0,1,2} selects Q/K/V.
// ---------------------------------------------------------------------------
__global__ __launch_bounds__(256) void qkv_gemm(
    const float* __restrict__ x,
    const float* __restrict__ Wq, const float* __restrict__ bq,
    const float* __restrict__ Wk, const float* __restrict__ bk,
    const float* __restrict__ Wv, const float* __restrict__ bv)
{
    const float* W;
    const float* bias;
    float* outp;
    if (blockIdx.z == 0)      { W = Wq; bias = bq; outp = g_q; }
    else if (blockIdx.z == 1) { W = Wk; bias = bk; outp = g_k; }
    else                      { W = Wv; bias = bv; outp = g_v; }

    __shared__ float As[16][64];   // [k][m]
    __shared__ float Ws[16][64];   // [k][n]

    const int tid = threadIdx.x;
    const int tx = tid & 15, ty = tid >> 4;
    const int bm = blockIdx.y * 64;
    const int bn = blockIdx.x * 64;

    const int arow = tid >> 2, aquad = tid & 3;    // A loader: 64 rows x 4 quads
    const int wrow = tid >> 4, wquad = tid & 15;   // W loader: 16 rows x 16 quads

    float acc[4][4] = {};

    for (int k0 = 0; k0 < D_MODEL; k0 += 16) {
        // Issue global loads before the sync so latency overlaps prior compute
        float4 av = *reinterpret_cast<const float4*>(x + (bm + arow) * D_MODEL + k0 + aquad * 4);
        float4 wv = *reinterpret_cast<const float4*>(W + (k0 + wrow) * D_MODEL + bn + wquad * 4);
        __syncthreads();
        As[aquad * 4 + 0][arow] = av.x;
        As[aquad * 4 + 1][arow] = av.y;
        As[aquad * 4 + 2][arow] = av.z;
        As[aquad * 4 + 3][arow] = av.w;
        *reinterpret_cast<float4*>(&Ws[wrow][wquad * 4]) = wv;
        __syncthreads();

#pragma unroll
        for (int k = 0; k < 16; ++k) {
            float4 a = *reinterpret_cast<const float4*>(&As[k][ty * 4]);
            float4 w = *reinterpret_cast<const float4*>(&Ws[k][tx * 4]);
            acc[0][0] += a.x * w.x; acc[0][1] += a.x * w.y; acc[0][2] += a.x * w.z; acc[0][3] += a.x * w.w;
            acc[1][0] += a.y * w.x; acc[1][1] += a.y * w.y; acc[1][2] += a.y * w.z; acc[1][3] += a.y * w.w;
            acc[2][0] += a.z * w.x; acc[2][1] += a.z * w.y; acc[2][2] += a.z * w.z; acc[2][3] += a.z * w.w;
            acc[3][0] += a.w * w.x; acc[3][1] += a.w * w.y; acc[3][2] += a.w * w.z; acc[3][3] += a.w * w.w;
        }
    }

    // N-tile == HD == 64, so head index == blockIdx.x
    const int h = blockIdx.x;
    const float4 bb = *reinterpret_cast<const float4*>(bias + bn + tx * 4);
#pragma unroll
    for (int i = 0; i < 4; ++i) {
        int m = bm + ty * 4 + i;
        int b_ = m >> 11;            // / SEQ
        int s_ = m & (SEQ - 1);
        float4 r;
        r.x = acc[i][0] + bb.x;
        r.y = acc[i][1] + bb.y;
        r.z = acc[i][2] + bb.z;
        r.w = acc[i][3] + bb.w;
        *reinterpret_cast<float4*>(outp + ((size_t)((b_ * NHEADS + h) * SEQ + s_)) * HD + tx * 4) = r;
    }
}

// ---------------------------------------------------------------------------
// Flash attention: one block = (b,h) x 64 query rows, loops over 32 key tiles.
// Q/K stored d-transposed in SMEM -> score loop is 2x LDS.128 + 16 FMA per d.
// Online softmax state (m, l) per row, in registers.
// ---------------------------------------------------------------------------
#define ATTN_SMEM ((3 * 64 * 64 + 64 * 65) * 4)

__global__ __launch_bounds__(256) void attn_kernel()
{
    extern __shared__ float sm[];
    float* Qt = sm;                 // [d][r]  64x64
    float* Kt = sm + 64 * 64;       // [d][c]  64x64
    float* Vs = sm + 2 * 64 * 64;   // [c][d]  64x64
    float* Pt = sm + 3 * 64 * 64;   // [c][r]  64x65 (pad: 2-way conflicts max)

    const int tid = threadIdx.x;
    const int tx = tid & 15, ty = tid >> 4;
    const int bh = blockIdx.y;                 // b*H + h
    const int q0 = blockIdx.x * 64;

    const float* Qg = g_q + ((size_t)bh * SEQ + q0) * HD;
    const float* Kg = g_k + (size_t)bh * SEQ * HD;
    const float* Vg = g_v + (size_t)bh * SEQ * HD;

    const float scale = 0.125f;   // 1/sqrt(64), folded into Q at load

    // Load Q tile transposed (and pre-scaled)
    for (int i = tid; i < 64 * 16; i += 256) {
        int r = i >> 4, quad = i & 15;
        float4 v = *reinterpret_cast<const float4*>(Qg + r * HD + quad * 4);
        Qt[(quad * 4 + 0) * 64 + r] = v.x * scale;
        Qt[(quad * 4 + 1) * 64 + r] = v.y * scale;
        Qt[(quad * 4 + 2) * 64 + r] = v.z * scale;
        Qt[(quad * 4 + 3) * 64 + r] = v.w * scale;
    }

    float o[4][4] = {};
    float mrow[4] = {-1e30f, -1e30f, -1e30f, -1e30f};
    float lrow[4] = {0.f, 0.f, 0.f, 0.f};

    for (int kt = 0; kt < SEQ / 64; ++kt) {
        const float* Kgt = Kg + kt * 64 * HD;
        const float* Vgt = Vg + kt * 64 * HD;

        __syncthreads();   // previous PV done with Vs/Pt, scores done with Kt
        for (int i = tid; i < 64 * 16; i += 256) {
            int r = i >> 4, quad = i & 15;
            float4 v = *reinterpret_cast<const float4*>(Kgt + r * HD + quad * 4);
            Kt[(quad * 4 + 0) * 64 + r] = v.x;
            Kt[(quad * 4 + 1) * 64 + r] = v.y;
            Kt[(quad * 4 + 2) * 64 + r] = v.z;
            Kt[(quad * 4 + 3) * 64 + r] = v.w;
            float4 vv = *reinterpret_cast<const float4*>(Vgt + r * HD + quad * 4);
            *reinterpret_cast<float4*>(&Vs[r * 64 + quad * 4]) = vv;
        }
        __syncthreads();

        // Scores: s[i][j] = sum_d Qt[d][4ty+i] * Kt[d][4tx+j]
        float s4[4][4] = {};
#pragma unroll 16
        for (int d = 0; d < 64; ++d) {
            float4 qv = *reinterpret_cast<const float4*>(&Qt[d * 64 + ty * 4]);
            float4 kv = *reinterpret_cast<const float4*>(&Kt[d * 64 + tx * 4]);
            s4[0][0] += qv.x * kv.x; s4[0][1] += qv.x * kv.y; s4[0][2] += qv.x * kv.z; s4[0][3] += qv.x * kv.w;
            s4[1][0] += qv.y * kv.x; s4[1][1] += qv.y * kv.y; s4[1][2] += qv.y * kv.z; s4[1][3] += qv.y * kv.w;
            s4[2][0] += qv.z * kv.x; s4[2][1] += qv.z * kv.y; s4[2][2] += qv.z * kv.z; s4[2][3] += qv.z * kv.w;
            s4[3][0] += qv.w * kv.x; s4[3][1] += qv.w * kv.y; s4[3][2] += qv.w * kv.z; s4[3][3] += qv.w * kv.w;
        }

        // Online softmax per row; xor-shuffle over the 16 tx lanes
#pragma unroll
        for (int i = 0; i < 4; ++i) {
            float mx = fmaxf(fmaxf(s4[i][0], s4[i][1]), fmaxf(s4[i][2], s4[i][3]));
#pragma unroll
            for (int off = 1; off <= 8; off <<= 1)
                mx = fmaxf(mx, __shfl_xor_sync(0xffffffffu, mx, off, 32));
            float mnew = fmaxf(mrow[i], mx);
            float alpha = __expf(mrow[i] - mnew);
            mrow[i] = mnew;
            float rs = 0.f;
#pragma unroll
            for (int j = 0; j < 4; ++j) {
                s4[i][j] = __expf(s4[i][j] - mnew);
                rs += s4[i][j];
            }
#pragma unroll
            for (int off = 1; off <= 8; off <<= 1)
                rs += __shfl_xor_sync(0xffffffffu, rs, off, 32);
            lrow[i] = lrow[i] * alpha + rs;
#pragma unroll
            for (int j = 0; j < 4; ++j) o[i][j] *= alpha;
            // Store P transposed: Pt[c][r]
#pragma unroll
            for (int j = 0; j < 4; ++j)
                Pt[(tx * 4 + j) * 65 + ty * 4 + i] = s4[i][j];
        }
        __syncthreads();

        // PV: o[i][j] += sum_c Pt[c][4ty+i] * Vs[c][4tx+j]
#pragma unroll 16
        for (int c = 0; c < 64; ++c) {
            float p0 = Pt[c * 65 + ty * 4 + 0];
            float p1 = Pt[c * 65 + ty * 4 + 1];
            float p2 = Pt[c * 65 + ty * 4 + 2];
            float p3 = Pt[c * 65 + ty * 4 + 3];
            float4 vv = *reinterpret_cast<const float4*>(&Vs[c * 64 + tx * 4]);
            o[0][0] += p0 * vv.x; o[0][1] += p0 * vv.y; o[0][2] += p0 * vv.z; o[0][3] += p0 * vv.w;
            o[1][0] += p1 * vv.x; o[1][1] += p1 * vv.y; o[1][2] += p1 * vv.z; o[1][3] += p1 * vv.w;
            o[2][0] += p2 * vv.x; o[2][1] += p2 * vv.y; o[2][2] += p2 * vv.z; o[2][3] += p2 * vv.w;
            o[3][0] += p3 * vv.x; o[3][1] += p3 * vv.y; o[3][2] += p3 * vv.z; o[3][3] += p3 * vv.w;
        }
    }

    // Epilogue: normalize and write attended in [b, s, h*HD+d] layout
    const int b_ = bh >> 4;
    const int h  = bh & 15;
#pragma unroll
    for (int i = 0; i < 4; ++i) {
        float inv = 1.0f / lrow[i];
        int q = q0 + ty * 4 + i;
        float4 r;
        r.x = o[i][0] * inv;
        r.y = o[i][1] * inv;
        r.z = o[i][2] * inv;
        r.w = o[i][3] * inv;
        *reinterpret_cast<float4*>(&g_att[((size_t)(b_ * SEQ + q)) * D_MODEL + h * HD + tx * 4]) = r;
    }
}

// ---------------------------------------------------------------------------
// Output projection: out = g_att @ Wo + bo   (row-major [4096,1024])
// ---------------------------------------------------------------------------
__global__ __launch_bounds__(256) void out_gemm(
    const float* __restrict__ Wo, const float* __restrict__ bo,
    float* __restrict__ out)
{
    __shared__ float As[16][64];
    __shared__ float Ws[16][64];

    const int tid = threadIdx.x;
    const int tx = tid & 15, ty = tid >> 4;
    const int bm = blockIdx.y * 64;
    const int bn = blockIdx.x * 64;

    const int arow = tid >> 2, aquad = tid & 3;
    const int wrow = tid >> 4, wquad = tid & 15;

    float acc[4][4] = {};

    for (int k0 = 0; k0 < D_MODEL; k0 += 16) {
        float4 av = *reinterpret_cast<const float4*>(g_att + ((size_t)(bm + arow)) * D_MODEL + k0 + aquad * 4);
        float4 wv = *reinterpret_cast<const float4*>(Wo + (k0 + wrow) * D_MODEL + bn + wquad * 4);
        __syncthreads();
        As[aquad * 4 + 0][arow] = av.x;
        As[aquad * 4 + 1][arow] = av.y;
        As[aquad * 4 + 2][arow] = av.z;
        As[aquad * 4 + 3][arow] = av.w;
        *reinterpret_cast<float4*>(&Ws[wrow][wquad * 4]) = wv;
        __syncthreads();

#pragma unroll
        for (int k = 0; k < 16; ++k) {
            float4 a = *reinterpret_cast<const float4*>(&As[k][ty * 4]);
            float4 w = *reinterpret_cast<const float4*>(&Ws[k][tx * 4]);
            acc[0][0] += a.x * w.x; acc[0][1] += a.x * w.y; acc[0][2] += a.x * w.z; acc[0][3] += a.x * w.w;
            acc[1][0] += a.y * w.x; acc[1][1] += a.y * w.y; acc[1][2] += a.y * w.z; acc[1][3] += a.y * w.w;
            acc[2][0] += a.z * w.x; acc[2][1] += a.z * w.y; acc[2][2] += a.z * w.z; acc[2][3] += a.z * w.w;
            acc[3][0] += a.w * w.x; acc[3][1] += a.w * w.y; acc[3][2] += a.w * w.z; acc[3][3] += a.w * w.w;
        }
    }

    const float4 bb = *reinterpret_cast<const float4*>(bo + bn + tx * 4);
#pragma unroll
    for (int i = 0; i < 4; ++i) {
        int m = bm + ty * 4 + i;
        float4 r;
        r.x = acc[i][0] + bb.x;
        r.y = acc[i][1] + bb.y;
        r.z = acc[i][2] + bb.z;
        r.w = acc[i][3] + bb.w;
        *reinterpret_cast<float4*>(out + (size_t)m * D_MODEL + bn + tx * 4) = r;
    }
}

// ---------------------------------------------------------------------------
extern "C" void kernel_launch(void* const* d_in, const int* in_sizes, int n_in,
                              void* d_out, int out_size)
{
    const float* x  = (const float*)d_in[0];
    const float* Wq = (const float*)d_in[1];
    const float* bq = (const float*)d_in[2];
    const float* Wk = (const float*)d_in[3];
    const float* bk = (const float*)d_in[4];
    const float* Wv = (const float*)d_in[5];
    const float* bv = (const float*)d_in[6];
    const float* Wo = (const float*)d_in[7];
    const float* bo = (const float*)d_in[8];
    float* out = (float*)d_out;

    // 1) QKV projections (fused over grid.z)
    dim3 g1(D_MODEL / 64, MTOT / 64, 3);   // 16 x 64 x 3
    qkv_gemm<<<g1, 256>>>(x, Wq, bq, Wk, bk, Wv, bv);

    // 2) Flash attention
    cudaFuncSetAttribute(attn_kernel, cudaFuncAttributeMaxDynamicSharedMemorySize, ATTN_SMEM);
    dim3 g2(SEQ / 64, BATCH * NHEADS);     // 32 x 32
    attn_kernel<<<g2, 256, ATTN_SMEM>>>();

    // 3) Output projection
    dim3 g3(D_MODEL / 64, MTOT / 64);      // 16 x 64
    out_gemm<<<g3, 256>>>(Wo, bo, out);
}